// round 16
// baseline (speedup 1.0000x reference)
#include <cuda_runtime.h>
#include <cuda_bf16.h>

#define NN 8192
#define ECAP (1u << 20)    // 1M compacted edge slots (4MB) — ~13x over ~78k
#define BUFCAP 4096u       // per-block smem staging (16KB)
#define OVF_CAP (1u << 16) // spill safety
#define FB 64              // finish blocks (all co-resident on 148 SMs)
#define FT 128             // finish threads/block; FB*FT == NN

// Static scratch. Counters reset by hc_finish each run.
__device__ unsigned int d_necnt;        // compacted edges
__device__ unsigned int d_dcount;       // diagonal positives
__device__ unsigned int d_edges[ECAP];  // (row<<13)|col
__device__ unsigned int d_ovfcnt;
__device__ unsigned int d_ovf[OVF_CAP];
__device__ int d_lab[NN];
__device__ unsigned int d_roots;
__device__ unsigned int d_chg[64];      // per-pass convergence flags (zeroed each run)
__device__ unsigned int d_bar_cnt;      // grid barrier state
__device__ unsigned int d_bar_gen;      // monotone generation (never reset)

// Upper-triangle scan, block per row pair (row, NN-1-row): NN+1 elements per
// block -> perfect balance. Hot loop: 4 batched LDG.128 + FMNMX max-tree +
// ONE FSETP + ballot — the exact positive count is computed only in the
// rare path (it doubles as the staging-buffer index bump). Block end: ONE
// global atomicAdd reserves a compacted range + coalesced copy-out.
// Exactness: adj bitwise symmetric -> full positives = 2U + D; the
// reference's sum(adj>0)//2 = U + D//2 exactly.
__global__ void __launch_bounds__(256) hc_scan(const float* __restrict__ adj) {
    __shared__ unsigned s_cnt;
    __shared__ unsigned s_base;
    __shared__ unsigned s_buf[BUFCAP];
    const int t = threadIdx.x;
    const int pair = blockIdx.x;
    if (t == 0) s_cnt = 0u;
    __syncthreads();

    #pragma unroll
    for (int half = 0; half < 2; half++) {
        const int row = half ? (NN - 1 - pair) : pair;
        const float4* __restrict__ rowp = (const float4*)(adj + (size_t)row * NN);
        const int start4 = row >> 2;            // quad containing the diagonal
        const unsigned enc_row = (unsigned)row << 13;

        if (t == 0) {
            // diagonal quad: cols may be <, ==, or > row
            float4 v = rowp[start4];
            int col0 = start4 << 2;
            float e[4] = {v.x, v.y, v.z, v.w};
            unsigned dd = 0;
            #pragma unroll
            for (int j = 0; j < 4; j++) {
                int col = col0 + j;
                if (e[j] > 0.0f) {
                    if (col == row) dd++;
                    else if (col > row) {
                        unsigned b = atomicAdd(&s_cnt, 1u);
                        if (b < BUFCAP) s_buf[b] = enc_row | (unsigned)col;
                        else {
                            unsigned o = atomicAdd(&d_ovfcnt, 1u);
                            if (o < OVF_CAP) d_ovf[o] = enc_row | (unsigned)col;
                        }
                    }
                }
            }
            if (dd) atomicAdd(&d_dcount, dd);
        }

        const int lim = NN / 4;
        for (int ib = start4 + 1; ib < lim; ib += 1024) {
            const float4 NEG = make_float4(-1.f, -1.f, -1.f, -1.f);
            const int i0 = ib + t;
            float4 v0 = NEG, v1 = NEG, v2 = NEG, v3 = NEG;
            if (i0       < lim) v0 = rowp[i0];
            if (i0 + 256 < lim) v1 = rowp[i0 + 256];
            if (i0 + 512 < lim) v2 = rowp[i0 + 512];
            if (i0 + 768 < lim) v3 = rowp[i0 + 768];

            // hot path: pure FMNMX tree + one compare (no counting)
            float m01 = fmaxf(fmaxf(v0.x, v0.y), fmaxf(v0.z, v0.w));
            float m11 = fmaxf(fmaxf(v1.x, v1.y), fmaxf(v1.z, v1.w));
            float m21 = fmaxf(fmaxf(v2.x, v2.y), fmaxf(v2.z, v2.w));
            float m31 = fmaxf(fmaxf(v3.x, v3.y), fmaxf(v3.z, v3.w));
            float mall = fmaxf(fmaxf(m01, m11), fmaxf(m21, m31));

            if (__ballot_sync(0xFFFFFFFFu, mall > 0.0f)) {
                if (mall > 0.0f) {
                    // rare path: exact count + emit (count == index bump)
                    unsigned k = (unsigned)(v0.x > 0.f) + (unsigned)(v0.y > 0.f)
                               + (unsigned)(v0.z > 0.f) + (unsigned)(v0.w > 0.f)
                               + (unsigned)(v1.x > 0.f) + (unsigned)(v1.y > 0.f)
                               + (unsigned)(v1.z > 0.f) + (unsigned)(v1.w > 0.f)
                               + (unsigned)(v2.x > 0.f) + (unsigned)(v2.y > 0.f)
                               + (unsigned)(v2.z > 0.f) + (unsigned)(v2.w > 0.f)
                               + (unsigned)(v3.x > 0.f) + (unsigned)(v3.y > 0.f)
                               + (unsigned)(v3.z > 0.f) + (unsigned)(v3.w > 0.f);
                    unsigned idx = atomicAdd(&s_cnt, k);
                    #pragma unroll
                    for (int q = 0; q < 4; q++) {
                        float4 v = (q == 0) ? v0 : (q == 1) ? v1 : (q == 2) ? v2 : v3;
                        int col0 = (i0 + q * 256) << 2;
                        float e[4] = {v.x, v.y, v.z, v.w};
                        #pragma unroll
                        for (int j = 0; j < 4; j++) {
                            if (e[j] > 0.f) {
                                if (idx < BUFCAP)
                                    s_buf[idx] = enc_row | (unsigned)(col0 + j);
                                else {
                                    unsigned o = atomicAdd(&d_ovfcnt, 1u);
                                    if (o < OVF_CAP) d_ovf[o] = enc_row | (unsigned)(col0 + j);
                                }
                                idx++;
                            }
                        }
                    }
                }
            }
        }
    }

    // compact: one global atomic per block, then coalesced copy-out
    __syncthreads();
    if (t == 0) {
        unsigned c = min(s_cnt, BUFCAP);
        s_base = atomicAdd(&d_necnt, c);
    }
    __syncthreads();
    unsigned c = min(s_cnt, BUFCAP);
    unsigned base = s_base;
    for (unsigned i = t; i < c; i += 256)
        if (base + i < ECAP) d_edges[base + i] = s_buf[i];
}

// Software grid barrier: sense-reversing on a monotone generation counter.
// FB=64 blocks always co-resident on 148 SMs -> deadlock-free.
__device__ __forceinline__ void grid_barrier() {
    __syncthreads();
    if (threadIdx.x == 0) {
        unsigned my = *(volatile unsigned*)&d_bar_gen;
        __threadfence();
        if (atomicAdd(&d_bar_cnt, 1u) == FB - 1u) {
            d_bar_cnt = 0u;
            __threadfence();
            atomicExch(&d_bar_gen, my + 1u);
        } else {
            while (*(volatile unsigned*)&d_bar_gen == my) { }
        }
        __threadfence();
    }
    __syncthreads();
}

// Coherent label read: atomics bypass L1, so label loads must go through L2.
__device__ __forceinline__ int lab_ld(int i) { return __ldcg(&d_lab[i]); }

// Distributed min-label CC: 8192 threads across 64 SMs, 1 node each.
// Per pass: stream the compacted edge list (coalesced uint4), push atomicMin
// to the larger endpoint when labels differ (monotone -> stale reads only
// cost extra passes, never false convergence thanks to __ldcg), then THREE
// pointer-jump rounds to compress label trees geometrically. Fixpoint =>
// labels constant per component => lab[i]==i exactly at component minima.
__global__ void __launch_bounds__(FT) hc_finish(float* __restrict__ out) {
    const int g = blockIdx.x * FT + threadIdx.x;   // node id, 0..NN-1

    d_lab[g] = g;
    grid_barrier();

    const unsigned n = min(d_necnt, ECAP);
    const unsigned novf = min(d_ovfcnt, OVF_CAP);
    const unsigned n4 = n >> 2;
    const uint4* e4p = (const uint4*)d_edges;

    for (int pass = 0; pass < 64; pass++) {
        int changed = 0;

        for (unsigned i = g; i < n4; i += (unsigned)(FB * FT)) {
            uint4 q = e4p[i];
            unsigned w[4] = {q.x, q.y, q.z, q.w};
            #pragma unroll
            for (int h = 0; h < 4; h++) {
                int u = (int)(w[h] >> 13), v = (int)(w[h] & 8191u);
                int lu = lab_ld(u), lv = lab_ld(v);
                if (lu != lv) {
                    changed = 1;
                    int mn = min(lu, lv);
                    if (lv != mn) atomicMin(&d_lab[v], mn);
                    else          atomicMin(&d_lab[u], mn);
                }
            }
        }
        for (unsigned i = (n4 << 2) + (unsigned)g; i < n; i += (unsigned)(FB * FT)) {
            unsigned e = d_edges[i];
            int u = (int)(e >> 13), v = (int)(e & 8191u);
            int lu = lab_ld(u), lv = lab_ld(v);
            if (lu != lv) {
                changed = 1;
                int mn = min(lu, lv);
                if (lv != mn) atomicMin(&d_lab[v], mn);
                else          atomicMin(&d_lab[u], mn);
            }
        }
        for (unsigned i = (unsigned)g; i < novf; i += (unsigned)(FB * FT)) {
            unsigned e = d_ovf[i];
            int u = (int)(e >> 13), v = (int)(e & 8191u);
            int lu = lab_ld(u), lv = lab_ld(v);
            if (lu != lv) {
                changed = 1;
                int mn = min(lu, lv);
                atomicMin(&d_lab[v], mn);
                atomicMin(&d_lab[u], mn);
            }
        }

        // pointer jump x3 (monotone; concurrent mins benign)
        #pragma unroll
        for (int r = 0; r < 3; r++) {
            int l = lab_ld(g);
            int ll = lab_ld(l);
            if (ll < l) atomicMin(&d_lab[g], ll);
        }

        int any = __syncthreads_or(changed);
        if (threadIdx.x == 0 && any) atomicOr(&d_chg[pass], 1u);
        grid_barrier();
        if (d_chg[pass] == 0u) break;
    }

    // count roots: lab[i]==i exactly at each component's min node
    int root = (lab_ld(g) == g) ? 1 : 0;
    int bsum = __syncthreads_count(root);
    if (threadIdx.x == 0) atomicAdd(&d_roots, (unsigned)bsum);
    grid_barrier();

    if (g == 0) {
        float n_comp  = (float)d_roots;
        unsigned U = d_necnt + d_ovfcnt;                // exact upper positives
        unsigned half_edges = U + (d_dcount >> 1);      // (2U+D)//2
        float n_edges = (float)half_edges;
        float betti1  = n_edges - (float)NN + n_comp;
        float n_cyc   = fmaxf(0.0f, betti1);
        float comp_l  = (n_comp - 1.0f) * (n_comp - 1.0f);
        out[0] = comp_l + n_cyc * n_cyc;
        // reset for the next replay
        d_necnt = 0u; d_dcount = 0u; d_ovfcnt = 0u; d_roots = 0u;
    }
    if (g < 64) d_chg[g] = 0u;
}

extern "C" void kernel_launch(void* const* d_in, const int* in_sizes, int n_in,
                              void* d_out, int out_size) {
    const float* adj = (const float*)d_in[0];
    float* out = (float*)d_out;

    hc_scan<<<NN / 2, 256>>>(adj);
    hc_finish<<<FB, FT>>>(out);
}

// round 17
// speedup vs baseline: 1.1444x; 1.1444x over previous
#include <cuda_runtime.h>
#include <cuda_bf16.h>

#define NN 8192
#define ECAP (1u << 20)    // 1M compacted edge slots (4MB) — ~13x over ~78k
#define BUFCAP 4096u       // per-block smem staging (16KB)
#define OVF_CAP (1u << 16) // spill safety
#define FB 64              // finish blocks (all co-resident on 148 SMs)
#define FT 128             // finish threads/block; FB*FT == NN
#define NTH (FB * FT)
#define GCACHE 4           // cached uint4 edge groups per thread (covers 128k edges)

// Static scratch. Counters reset by hc_finish each run.
__device__ unsigned int d_necnt;        // compacted edges
__device__ unsigned int d_dcount;       // diagonal positives
__device__ unsigned int d_edges[ECAP];  // (row<<13)|col
__device__ unsigned int d_ovfcnt;
__device__ unsigned int d_ovf[OVF_CAP];
__device__ int d_lab[NN];
__device__ unsigned int d_roots;
__device__ unsigned int d_chg[64];      // per-pass convergence flags (zeroed each run)
__device__ unsigned int d_bar_cnt;      // grid barrier state
__device__ unsigned int d_bar_gen;      // monotone generation (never reset)

// Upper-triangle scan, block per row pair (row, NN-1-row): NN+1 elements per
// block -> perfect balance. Hot loop: 4 batched LDG.128 + FMNMX max-tree +
// ONE FSETP + ballot — exact counting only on the rare path (it doubles as
// the staging-buffer index bump). Block end: ONE global atomicAdd reserves
// a compacted range + coalesced copy-out. (Measured 30.6us, 4.3 TB/s.)
// Exactness: adj bitwise symmetric -> full positives = 2U + D; the
// reference's sum(adj>0)//2 = U + D//2 exactly.
__global__ void __launch_bounds__(256) hc_scan(const float* __restrict__ adj) {
    __shared__ unsigned s_cnt;
    __shared__ unsigned s_base;
    __shared__ unsigned s_buf[BUFCAP];
    const int t = threadIdx.x;
    const int pair = blockIdx.x;
    if (t == 0) s_cnt = 0u;
    __syncthreads();

    #pragma unroll
    for (int half = 0; half < 2; half++) {
        const int row = half ? (NN - 1 - pair) : pair;
        const float4* __restrict__ rowp = (const float4*)(adj + (size_t)row * NN);
        const int start4 = row >> 2;            // quad containing the diagonal
        const unsigned enc_row = (unsigned)row << 13;

        if (t == 0) {
            // diagonal quad: cols may be <, ==, or > row
            float4 v = rowp[start4];
            int col0 = start4 << 2;
            float e[4] = {v.x, v.y, v.z, v.w};
            unsigned dd = 0;
            #pragma unroll
            for (int j = 0; j < 4; j++) {
                int col = col0 + j;
                if (e[j] > 0.0f) {
                    if (col == row) dd++;
                    else if (col > row) {
                        unsigned b = atomicAdd(&s_cnt, 1u);
                        if (b < BUFCAP) s_buf[b] = enc_row | (unsigned)col;
                        else {
                            unsigned o = atomicAdd(&d_ovfcnt, 1u);
                            if (o < OVF_CAP) d_ovf[o] = enc_row | (unsigned)col;
                        }
                    }
                }
            }
            if (dd) atomicAdd(&d_dcount, dd);
        }

        const int lim = NN / 4;
        for (int ib = start4 + 1; ib < lim; ib += 1024) {
            const float4 NEG = make_float4(-1.f, -1.f, -1.f, -1.f);
            const int i0 = ib + t;
            float4 v0 = NEG, v1 = NEG, v2 = NEG, v3 = NEG;
            if (i0       < lim) v0 = rowp[i0];
            if (i0 + 256 < lim) v1 = rowp[i0 + 256];
            if (i0 + 512 < lim) v2 = rowp[i0 + 512];
            if (i0 + 768 < lim) v3 = rowp[i0 + 768];

            float m01 = fmaxf(fmaxf(v0.x, v0.y), fmaxf(v0.z, v0.w));
            float m11 = fmaxf(fmaxf(v1.x, v1.y), fmaxf(v1.z, v1.w));
            float m21 = fmaxf(fmaxf(v2.x, v2.y), fmaxf(v2.z, v2.w));
            float m31 = fmaxf(fmaxf(v3.x, v3.y), fmaxf(v3.z, v3.w));
            float mall = fmaxf(fmaxf(m01, m11), fmaxf(m21, m31));

            if (__ballot_sync(0xFFFFFFFFu, mall > 0.0f)) {
                if (mall > 0.0f) {
                    unsigned k = (unsigned)(v0.x > 0.f) + (unsigned)(v0.y > 0.f)
                               + (unsigned)(v0.z > 0.f) + (unsigned)(v0.w > 0.f)
                               + (unsigned)(v1.x > 0.f) + (unsigned)(v1.y > 0.f)
                               + (unsigned)(v1.z > 0.f) + (unsigned)(v1.w > 0.f)
                               + (unsigned)(v2.x > 0.f) + (unsigned)(v2.y > 0.f)
                               + (unsigned)(v2.z > 0.f) + (unsigned)(v2.w > 0.f)
                               + (unsigned)(v3.x > 0.f) + (unsigned)(v3.y > 0.f)
                               + (unsigned)(v3.z > 0.f) + (unsigned)(v3.w > 0.f);
                    unsigned idx = atomicAdd(&s_cnt, k);
                    #pragma unroll
                    for (int q = 0; q < 4; q++) {
                        float4 v = (q == 0) ? v0 : (q == 1) ? v1 : (q == 2) ? v2 : v3;
                        int col0 = (i0 + q * 256) << 2;
                        float e[4] = {v.x, v.y, v.z, v.w};
                        #pragma unroll
                        for (int j = 0; j < 4; j++) {
                            if (e[j] > 0.f) {
                                if (idx < BUFCAP)
                                    s_buf[idx] = enc_row | (unsigned)(col0 + j);
                                else {
                                    unsigned o = atomicAdd(&d_ovfcnt, 1u);
                                    if (o < OVF_CAP) d_ovf[o] = enc_row | (unsigned)(col0 + j);
                                }
                                idx++;
                            }
                        }
                    }
                }
            }
        }
    }

    // compact: one global atomic per block, then coalesced copy-out
    __syncthreads();
    if (t == 0) {
        unsigned c = min(s_cnt, BUFCAP);
        s_base = atomicAdd(&d_necnt, c);
    }
    __syncthreads();
    unsigned c = min(s_cnt, BUFCAP);
    unsigned base = s_base;
    for (unsigned i = t; i < c; i += 256)
        if (base + i < ECAP) d_edges[base + i] = s_buf[i];
}

// Software grid barrier: sense-reversing on a monotone generation counter.
// FB=64 blocks always co-resident on 148 SMs -> deadlock-free.
__device__ __forceinline__ void grid_barrier() {
    __syncthreads();
    if (threadIdx.x == 0) {
        unsigned my = *(volatile unsigned*)&d_bar_gen;
        __threadfence();
        if (atomicAdd(&d_bar_cnt, 1u) == FB - 1u) {
            d_bar_cnt = 0u;
            __threadfence();
            atomicExch(&d_bar_gen, my + 1u);
        } else {
            while (*(volatile unsigned*)&d_bar_gen == my) { }
        }
        __threadfence();
    }
    __syncthreads();
}

// Coherent (L2) label read — atomics are L2-visible, plain .ca loads aren't.
__device__ __forceinline__ int lab_ld(int i) { return __ldcg(&d_lab[i]); }

// Distributed min-label CC: 8192 threads on 64 SMs, 1 node each.
// Edge groups cached in registers ONCE (no per-pass L2 edge re-reads).
// Per pass: per group, 8 label loads issued back-to-back (one L2 round-trip)
// then compare + fire-and-forget atomicMin; per node, jump-to-root (full
// path compression, monotone) so label trees collapse each pass ->
// ~3-4 passes + 1 confirm. Fixpoint => labels constant per component =>
// lab[i]==i exactly at component minima.
__global__ void __launch_bounds__(FT) hc_finish(float* __restrict__ out) {
    const int g = blockIdx.x * FT + threadIdx.x;   // node id, 0..NN-1

    d_lab[g] = g;

    // cache this thread's edge groups in registers (grid-stride over groups)
    const unsigned n = min(d_necnt, ECAP);
    const unsigned novf = min(d_ovfcnt, OVF_CAP);
    const unsigned n4 = n >> 2;
    const uint4* e4p = (const uint4*)d_edges;

    uint4 E[GCACHE];
    int ng = 0;
    for (unsigned i = (unsigned)g; i < n4 && ng < GCACHE; i += NTH)
        E[ng++] = e4p[i];

    grid_barrier();

    for (int pass = 0; pass < 64; pass++) {
        int changed = 0;

        for (int c = 0; c < ng; c++) {
            unsigned w0 = E[c].x, w1 = E[c].y, w2 = E[c].z, w3 = E[c].w;
            int u0 = (int)(w0 >> 13), v0 = (int)(w0 & 8191u);
            int u1 = (int)(w1 >> 13), v1 = (int)(w1 & 8191u);
            int u2 = (int)(w2 >> 13), v2 = (int)(w2 & 8191u);
            int u3 = (int)(w3 >> 13), v3 = (int)(w3 & 8191u);
            // 8 independent coherent loads, one L2 round-trip
            int a0 = lab_ld(u0), b0 = lab_ld(v0);
            int a1 = lab_ld(u1), b1 = lab_ld(v1);
            int a2 = lab_ld(u2), b2 = lab_ld(v2);
            int a3 = lab_ld(u3), b3 = lab_ld(v3);
            if (a0 != b0) { changed = 1; int mn = min(a0, b0);
                            if (b0 != mn) atomicMin(&d_lab[v0], mn); else atomicMin(&d_lab[u0], mn); }
            if (a1 != b1) { changed = 1; int mn = min(a1, b1);
                            if (b1 != mn) atomicMin(&d_lab[v1], mn); else atomicMin(&d_lab[u1], mn); }
            if (a2 != b2) { changed = 1; int mn = min(a2, b2);
                            if (b2 != mn) atomicMin(&d_lab[v2], mn); else atomicMin(&d_lab[u2], mn); }
            if (a3 != b3) { changed = 1; int mn = min(a3, b3);
                            if (b3 != mn) atomicMin(&d_lab[v3], mn); else atomicMin(&d_lab[u3], mn); }
        }
        // uncached remainder (only if >128k edges), tail, overflow
        for (unsigned i = (unsigned)g + (unsigned)GCACHE * NTH; i < n4; i += NTH) {
            uint4 q = e4p[i];
            unsigned w[4] = {q.x, q.y, q.z, q.w};
            #pragma unroll
            for (int h = 0; h < 4; h++) {
                int u = (int)(w[h] >> 13), v = (int)(w[h] & 8191u);
                int lu = lab_ld(u), lv = lab_ld(v);
                if (lu != lv) { changed = 1; int mn = min(lu, lv);
                                if (lv != mn) atomicMin(&d_lab[v], mn); else atomicMin(&d_lab[u], mn); }
            }
        }
        for (unsigned i = (n4 << 2) + (unsigned)g; i < n; i += NTH) {
            unsigned e = d_edges[i];
            int u = (int)(e >> 13), v = (int)(e & 8191u);
            int lu = lab_ld(u), lv = lab_ld(v);
            if (lu != lv) { changed = 1; int mn = min(lu, lv);
                            if (lv != mn) atomicMin(&d_lab[v], mn); else atomicMin(&d_lab[u], mn); }
        }
        for (unsigned i = (unsigned)g; i < novf; i += NTH) {
            unsigned e = d_ovf[i];
            int u = (int)(e >> 13), v = (int)(e & 8191u);
            int lu = lab_ld(u), lv = lab_ld(v);
            if (lu != lv) { changed = 1; int mn = min(lu, lv);
                            atomicMin(&d_lab[v], mn); atomicMin(&d_lab[u], mn); }
        }

        // jump-to-root: full path compression (monotone chase, bounded)
        {
            int l = lab_ld(g);
            int ll = lab_ld(l);
            while (ll != l) { l = ll; ll = lab_ld(l); }
            atomicMin(&d_lab[g], l);
        }

        int any = __syncthreads_or(changed);
        if (threadIdx.x == 0 && any) atomicOr(&d_chg[pass], 1u);
        grid_barrier();
        if (d_chg[pass] == 0u) break;
    }

    // count roots: lab[i]==i exactly at each component's min node
    int root = (lab_ld(g) == g) ? 1 : 0;
    int bsum = __syncthreads_count(root);
    if (threadIdx.x == 0) atomicAdd(&d_roots, (unsigned)bsum);
    grid_barrier();

    if (g == 0) {
        float n_comp  = (float)d_roots;
        unsigned U = d_necnt + d_ovfcnt;                // exact upper positives
        unsigned half_edges = U + (d_dcount >> 1);      // (2U+D)//2
        float n_edges = (float)half_edges;
        float betti1  = n_edges - (float)NN + n_comp;
        float n_cyc   = fmaxf(0.0f, betti1);
        float comp_l  = (n_comp - 1.0f) * (n_comp - 1.0f);
        out[0] = comp_l + n_cyc * n_cyc;
        // reset for the next replay
        d_necnt = 0u; d_dcount = 0u; d_ovfcnt = 0u; d_roots = 0u;
    }
    if (g < 64) d_chg[g] = 0u;
}

extern "C" void kernel_launch(void* const* d_in, const int* in_sizes, int n_in,
                              void* d_out, int out_size) {
    const float* adj = (const float*)d_in[0];
    float* out = (float*)d_out;

    hc_scan<<<NN / 2, 256>>>(adj);
    hc_finish<<<FB, FT>>>(out);
}